// round 16
// baseline (speedup 1.0000x reference)
#include <cuda_runtime.h>
#include <cuda_bf16.h>
#include <math.h>

// Problem constants
#define H_NF 128
#define N_GAUSS 50
#define MAX_NODES 100000

#define EPB 512   // edges per block
#define TPB 256   // threads per block
#define EPW 64    // edges per warp (512 / 8 warps)

// step = 10/49 ; exp(coeff*(d-o)^2) = 2^( -(A*d - A*o)^2 ), A = sqrt(0.5*log2e)/step
#define STEP_D    (10.0 / 49.0)
#define A_CONST   ((float)(0.8493255219056067 / STEP_D))
#define AS_CONST  ((float)0.8493255219056067)

// Padded coords scratch: [N] float4. Static device array (no alloc).
__device__ float4 g_coords4[MAX_NODES];

// ---------------------------------------------------------------------------
// Prologue: pad coords [N,3] -> float4 [N]
// ---------------------------------------------------------------------------
__global__ void pad_coords_kernel(const float* __restrict__ coords, int n_nodes) {
    int i = blockIdx.x * blockDim.x + threadIdx.x;
    if (i < n_nodes) {
        float4 v;
        v.x = __ldg(&coords[(size_t)i * 3 + 0]);
        v.y = __ldg(&coords[(size_t)i * 3 + 1]);
        v.z = __ldg(&coords[(size_t)i * 3 + 2]);
        v.w = 0.0f;
        g_coords4[i] = v;
    }
}

// ---------------------------------------------------------------------------
// Fused kernel. Node-embedding blocks FIRST (low blockIdx) so the grid's tail
// waves are high-throughput edge blocks, not latency-bound node gathers.
// Edge blocks: warp-local pipeline (R6 winner, unchanged).
// ---------------------------------------------------------------------------
__global__ __launch_bounds__(TPB) void fused_kernel(
    const int*   __restrict__ atomic_ns,   // [N]
    const int*   __restrict__ edge_index,  // [2, E]
    const float4* __restrict__ weight4,    // [100, 32] as float4
    float4* __restrict__ out_node4,        // [N, 32] as float4
    float*  __restrict__ out_eembs,        // [E, 50]
    float*  __restrict__ out_ew,           // [E]
    long long n_edges,
    int n_nodes,
    int node_blocks)
{
    const int tid = threadIdx.x;

    // ---------------- node-embedding blocks (first in launch order) --------
    if (blockIdx.x < node_blocks) {
        int node = blockIdx.x * (TPB / 32) + (tid >> 5);
        int lane = tid & 31;
        if (node < n_nodes) {
            int a = __ldg(&atomic_ns[node]);
            float4 v = __ldg(&weight4[(size_t)a * 32 + lane]);
            __stcs(&out_node4[(size_t)node * 32 + lane], v);
        }
        return;
    }

    // ---------------- edge blocks ----------------
    __shared__ float s_dist[EPB + 8];

    const long long e0 = (long long)(blockIdx.x - node_blocks) * EPB;
    const bool full = (e0 + EPB) <= n_edges;

    if (full) {
        // Warp-local pipeline: no block barrier. Warp w owns 64 edges.
        const int w    = tid >> 5;
        const int lane = tid & 31;
        float* s_seg = s_dist + w * EPW;
        const long long we0 = e0 + (long long)w * EPW;

        // Phase 1 (warp): gather + distance for edges [we0, we0+64)
        {
            long long eA = we0 + lane;
            long long eB = eA + 32;
            int iA = __ldcg(&edge_index[eA]);
            int jA = __ldcg(&edge_index[n_edges + eA]);
            int iB = __ldcg(&edge_index[eB]);
            int jB = __ldcg(&edge_index[n_edges + eB]);
            float4 a0 = __ldcg(&g_coords4[iA]);
            float4 b0 = __ldcg(&g_coords4[jA]);
            float4 a1 = __ldcg(&g_coords4[iB]);
            float4 b1 = __ldcg(&g_coords4[jB]);
            float dx0 = a0.x - b0.x, dy0 = a0.y - b0.y, dz0 = a0.z - b0.z;
            float dx1 = a1.x - b1.x, dy1 = a1.y - b1.y, dz1 = a1.z - b1.z;
            float dist0 = sqrtf(fmaf(dx0, dx0, fmaf(dy0, dy0, dz0 * dz0)));
            float dist1 = sqrtf(fmaf(dx1, dx1, fmaf(dy1, dy1, dz1 * dz1)));
            __stcs(&out_ew[eA], dist0);
            __stcs(&out_ew[eB], dist1);
            s_seg[lane]      = dist0 * A_CONST;
            s_seg[lane + 32] = dist1 * A_CONST;
        }
        __syncwarp();

        // Phase 2 (warp): 64 edges * 50 floats = 800 float4, 25 per lane.
        float4* __restrict__ base4 =
            reinterpret_cast<float4*>(out_eembs + we0 * N_GAUSS);
        int f  = 4 * lane;
        int le = f / 50;            // 0..63 within warp segment
        int g  = f - 50 * le;
        #pragma unroll
        for (int it = 0; it < 25; ++it) {
            float u  = s_seg[le];
            bool span = (g == 48);
            float un = 0.0f;
            if (span) un = s_seg[le + 1];   // never crosses segment
            float og = (float)g * AS_CONST;
            float d0 = u - og;
            float d1 = d0 - AS_CONST;
            float d2 = span ? un : (d1 - AS_CONST);
            float d3 = d2 - AS_CONST;
            float4 r;
            r.x = exp2f(d0 * -d0);
            r.y = exp2f(d1 * -d1);
            r.z = exp2f(d2 * -d2);
            r.w = exp2f(d3 * -d3);
            __stcs(&base4[lane + it * 32], r);
            // advance flat float index by 128: +2 edges, +28 gauss
            g += 28; le += 2;
            if (g >= 50) { g -= 50; le += 1; }
        }
    } else {
        // Guarded tail block (rare): block-wide with barrier.
        if (tid < 8) s_dist[EPB + tid] = 0.0f;
        #pragma unroll
        for (int s = 0; s < EPB / TPB; ++s) {
            long long e = e0 + tid + s * TPB;
            if (e < n_edges) {
                int i = __ldcg(&edge_index[e]);
                int j = __ldcg(&edge_index[n_edges + e]);
                float4 a = __ldcg(&g_coords4[i]);
                float4 b = __ldcg(&g_coords4[j]);
                float dx = a.x - b.x, dy = a.y - b.y, dz = a.z - b.z;
                float dist = sqrtf(fmaf(dx, dx, fmaf(dy, dy, dz * dz)));
                __stcs(&out_ew[e], dist);
                s_dist[tid + s * TPB] = dist * A_CONST;
            } else {
                s_dist[tid + s * TPB] = 0.0f;
            }
        }
        __syncthreads();
        int rem = (int)(n_edges - e0);
        int total = rem * (N_GAUSS / 2);
        float2* __restrict__ base2 =
            reinterpret_cast<float2*>(out_eembs + e0 * N_GAUSS);
        for (int k = tid; k < total; k += TPB) {
            int le = k / 25;
            int p  = k - le * 25;
            float u  = s_dist[le];
            float o0 = (float)(2 * p) * AS_CONST;
            float d0 = u - o0;
            float d1 = d0 - AS_CONST;
            float2 r;
            r.x = exp2f(d0 * -d0);
            r.y = exp2f(d1 * -d1);
            __stcs(&base2[k], r);
        }
    }
}

// ---------------------------------------------------------------------------
// Inputs (metadata order):
//   0: atomic_ns int32 [N], 1: edge_index int32 [2,E], 2: coords f32 [N,3],
//   3: batch_node_vec int32 [N] (unused), 4: node_emb_weight f32 [100,128]
// Output (f32): node_embs [N,128] | edge_embs [E,50] | edge_weights [E]
// ---------------------------------------------------------------------------
extern "C" void kernel_launch(void* const* d_in, const int* in_sizes, int n_in,
                              void* d_out, int out_size) {
    const int*   atomic_ns  = (const int*)d_in[0];
    const int*   edge_index = (const int*)d_in[1];
    const float* coords     = (const float*)d_in[2];
    const float* weight     = (const float*)d_in[4];

    const int       n_nodes = in_sizes[0];
    const long long n_edges = (long long)in_sizes[1] / 2;

    float* out = (float*)d_out;
    float* out_node  = out;
    float* out_eembs = out + (size_t)n_nodes * H_NF;
    float* out_ew    = out_eembs + (size_t)n_edges * N_GAUSS;

    // Prologue: pad coords into float4 scratch
    {
        int tpb = 256;
        int blocks = (n_nodes + tpb - 1) / tpb;
        pad_coords_kernel<<<blocks, tpb>>>(coords, n_nodes);
    }

    int edge_blocks = (int)((n_edges + EPB - 1) / EPB);
    int node_blocks = (n_nodes + (TPB / 32) - 1) / (TPB / 32);

    fused_kernel<<<node_blocks + edge_blocks, TPB>>>(
        atomic_ns, edge_index,
        (const float4*)weight,
        (float4*)out_node, out_eembs, out_ew,
        n_edges, n_nodes, node_blocks);
}

// round 17
// speedup vs baseline: 1.0200x; 1.0200x over previous
#include <cuda_runtime.h>
#include <cuda_bf16.h>
#include <math.h>

// Problem constants
#define H_NF 128
#define N_GAUSS 50
#define MAX_NODES 100000

#define EPB 512   // edges per block
#define TPB 256   // threads per block
#define EPW 64    // edges per warp (512 / 8 warps)

// step = 10/49 ; exp(coeff*(d-o)^2) = 2^( -(A*d - A*o)^2 ), A = sqrt(0.5*log2e)/step
#define STEP_D    (10.0 / 49.0)
#define A_CONST   ((float)(0.8493255219056067 / STEP_D))
#define AS_CONST  ((float)0.8493255219056067)

// Padded coords scratch: [N] float4. Static device array (no alloc).
__device__ float4 g_coords4[MAX_NODES];

// ---------------------------------------------------------------------------
// Prologue: pad coords [N,3] -> float4 [N]
// ---------------------------------------------------------------------------
__global__ void pad_coords_kernel(const float* __restrict__ coords, int n_nodes) {
    int i = blockIdx.x * blockDim.x + threadIdx.x;
    if (i < n_nodes) {
        float4 v;
        v.x = __ldg(&coords[(size_t)i * 3 + 0]);
        v.y = __ldg(&coords[(size_t)i * 3 + 1]);
        v.z = __ldg(&coords[(size_t)i * 3 + 2]);
        v.w = 0.0f;
        g_coords4[i] = v;
    }
}

// ---------------------------------------------------------------------------
// Fused: node-embedding gather blocks + edge blocks (warp-local pipeline)
// ---------------------------------------------------------------------------
__global__ __launch_bounds__(TPB) void fused_kernel(
    const int*   __restrict__ atomic_ns,   // [N]
    const int*   __restrict__ edge_index,  // [2, E]
    const float4* __restrict__ weight4,    // [100, 32] as float4
    float4* __restrict__ out_node4,        // [N, 32] as float4
    float*  __restrict__ out_eembs,        // [E, 50]
    float*  __restrict__ out_ew,           // [E]
    long long n_edges,
    int n_nodes,
    int edge_blocks)
{
    const int tid = threadIdx.x;

    // ---------------- node-embedding blocks ----------------
    if (blockIdx.x >= edge_blocks) {
        int nb   = blockIdx.x - edge_blocks;
        int node = nb * (TPB / 32) + (tid >> 5);
        int lane = tid & 31;
        if (node < n_nodes) {
            int a = __ldg(&atomic_ns[node]);
            float4 v = __ldg(&weight4[(size_t)a * 32 + lane]);
            __stcs(&out_node4[(size_t)node * 32 + lane], v);
        }
        return;
    }

    // ---------------- edge blocks ----------------
    __shared__ float s_dist[EPB + 8];

    const long long e0 = (long long)blockIdx.x * EPB;
    const bool full = (e0 + EPB) <= n_edges;

    if (full) {
        // Warp-local pipeline: no block barrier. Warp w owns 64 edges.
        const int w    = tid >> 5;
        const int lane = tid & 31;
        float* s_seg = s_dist + w * EPW;
        const long long we0 = e0 + (long long)w * EPW;

        // Phase 1 (warp): gather + distance for edges [we0, we0+64)
        {
            long long eA = we0 + lane;
            long long eB = eA + 32;
            int iA = __ldcg(&edge_index[eA]);
            int jA = __ldcg(&edge_index[n_edges + eA]);
            int iB = __ldcg(&edge_index[eB]);
            int jB = __ldcg(&edge_index[n_edges + eB]);
            float4 a0 = __ldcg(&g_coords4[iA]);
            float4 b0 = __ldcg(&g_coords4[jA]);
            float4 a1 = __ldcg(&g_coords4[iB]);
            float4 b1 = __ldcg(&g_coords4[jB]);
            float dx0 = a0.x - b0.x, dy0 = a0.y - b0.y, dz0 = a0.z - b0.z;
            float dx1 = a1.x - b1.x, dy1 = a1.y - b1.y, dz1 = a1.z - b1.z;
            float dist0 = sqrtf(fmaf(dx0, dx0, fmaf(dy0, dy0, dz0 * dz0)));
            float dist1 = sqrtf(fmaf(dx1, dx1, fmaf(dy1, dy1, dz1 * dz1)));
            __stcs(&out_ew[eA], dist0);
            __stcs(&out_ew[eB], dist1);
            s_seg[lane]      = dist0 * A_CONST;
            s_seg[lane + 32] = dist1 * A_CONST;
        }
        __syncwarp();

        // Phase 2 (warp): 64 edges * 50 floats = 800 float4, 25 per lane.
        float4* __restrict__ base4 =
            reinterpret_cast<float4*>(out_eembs + we0 * N_GAUSS);
        int f  = 4 * lane;
        int le = f / 50;            // 0..63 within warp segment
        int g  = f - 50 * le;
        #pragma unroll
        for (int it = 0; it < 25; ++it) {
            float u  = s_seg[le];
            bool span = (g == 48);
            float un = 0.0f;
            if (span) un = s_seg[le + 1];   // never crosses segment
            float og = (float)g * AS_CONST;
            float d0 = u - og;
            float d1 = d0 - AS_CONST;
            float d2 = span ? un : (d1 - AS_CONST);
            float d3 = d2 - AS_CONST;
            float4 r;
            r.x = exp2f(d0 * -d0);
            r.y = exp2f(d1 * -d1);
            r.z = exp2f(d2 * -d2);
            r.w = exp2f(d3 * -d3);
            __stcs(&base4[lane + it * 32], r);
            // advance flat float index by 128: +2 edges, +28 gauss
            g += 28; le += 2;
            if (g >= 50) { g -= 50; le += 1; }
        }
    } else {
        // Guarded tail block (rare): block-wide with barrier.
        if (tid < 8) s_dist[EPB + tid] = 0.0f;
        #pragma unroll
        for (int s = 0; s < EPB / TPB; ++s) {
            long long e = e0 + tid + s * TPB;
            if (e < n_edges) {
                int i = __ldcg(&edge_index[e]);
                int j = __ldcg(&edge_index[n_edges + e]);
                float4 a = __ldcg(&g_coords4[i]);
                float4 b = __ldcg(&g_coords4[j]);
                float dx = a.x - b.x, dy = a.y - b.y, dz = a.z - b.z;
                float dist = sqrtf(fmaf(dx, dx, fmaf(dy, dy, dz * dz)));
                __stcs(&out_ew[e], dist);
                s_dist[tid + s * TPB] = dist * A_CONST;
            } else {
                s_dist[tid + s * TPB] = 0.0f;
            }
        }
        __syncthreads();
        int rem = (int)(n_edges - e0);
        int total = rem * (N_GAUSS / 2);
        float2* __restrict__ base2 =
            reinterpret_cast<float2*>(out_eembs + e0 * N_GAUSS);
        for (int k = tid; k < total; k += TPB) {
            int le = k / 25;
            int p  = k - le * 25;
            float u  = s_dist[le];
            float o0 = (float)(2 * p) * AS_CONST;
            float d0 = u - o0;
            float d1 = d0 - AS_CONST;
            float2 r;
            r.x = exp2f(d0 * -d0);
            r.y = exp2f(d1 * -d1);
            __stcs(&base2[k], r);
        }
    }
}

// ---------------------------------------------------------------------------
// Inputs (metadata order):
//   0: atomic_ns int32 [N], 1: edge_index int32 [2,E], 2: coords f32 [N,3],
//   3: batch_node_vec int32 [N] (unused), 4: node_emb_weight f32 [100,128]
// Output (f32): node_embs [N,128] | edge_embs [E,50] | edge_weights [E]
// ---------------------------------------------------------------------------
extern "C" void kernel_launch(void* const* d_in, const int* in_sizes, int n_in,
                              void* d_out, int out_size) {
    const int*   atomic_ns  = (const int*)d_in[0];
    const int*   edge_index = (const int*)d_in[1];
    const float* coords     = (const float*)d_in[2];
    const float* weight     = (const float*)d_in[4];

    const int       n_nodes = in_sizes[0];
    const long long n_edges = (long long)in_sizes[1] / 2;

    float* out = (float*)d_out;
    float* out_node  = out;
    float* out_eembs = out + (size_t)n_nodes * H_NF;
    float* out_ew    = out_eembs + (size_t)n_edges * N_GAUSS;

    // Prologue: pad coords into float4 scratch
    {
        int tpb = 256;
        int blocks = (n_nodes + tpb - 1) / tpb;
        pad_coords_kernel<<<blocks, tpb>>>(coords, n_nodes);
    }

    int edge_blocks = (int)((n_edges + EPB - 1) / EPB);
    int node_blocks = (n_nodes + (TPB / 32) - 1) / (TPB / 32);

    fused_kernel<<<edge_blocks + node_blocks, TPB>>>(
        atomic_ns, edge_index,
        (const float4*)weight,
        (float4*)out_node, out_eembs, out_ew,
        n_edges, n_nodes, edge_blocks);
}